// round 6
// baseline (speedup 1.0000x reference)
#include <cuda_runtime.h>
#include <math.h>

#define Hs    64
#define SEQ   2048
#define Bt    256
#define IN    32
#define GATES 256   // 4*H

typedef unsigned long long u64;

__device__ float g_xproj[(size_t)SEQ * Bt * GATES];   // [t][row][g], bias0 folded

__device__ __forceinline__ u64 fma2(u64 a, u64 b, u64 c) {
    u64 d;
    asm("fma.rn.f32x2 %0, %1, %2, %3;" : "=l"(d) : "l"(a), "l"(b), "l"(c));
    return d;
}
__device__ __forceinline__ u64 pk(float a, float b) {
    u64 r;
    asm("mov.b64 %0, {%1, %2};" : "=l"(r) : "f"(a), "f"(b));
    return r;
}
__device__ __forceinline__ float hsum(u64 v) {
    float a, b;
    asm("mov.b64 {%0, %1}, %2;" : "=f"(a), "=f"(b) : "l"(v));
    return a + b;
}
__device__ __forceinline__ float ex2a(float x) {
    float y; asm("ex2.approx.f32 %0, %1;" : "=f"(y) : "f"(x)); return y;
}
__device__ __forceinline__ float rcpa(float x) {
    float y; asm("rcp.approx.f32 %0, %1;" : "=f"(y) : "f"(x)); return y;
}
__device__ __forceinline__ float sigf(float x) {
    return rcpa(1.0f + ex2a(-1.4426950408889634f * x));
}
__device__ __forceinline__ float tanhfa(float x) {
    return fmaf(2.0f, sigf(2.0f * x), -1.0f);
}
__device__ __forceinline__ void cpasync16(void* smem_dst, const void* gsrc) {
    unsigned s = (unsigned)__cvta_generic_to_shared(smem_dst);
    asm volatile("cp.async.ca.shared.global [%0], [%1], 16;" :: "r"(s), "l"(gsrc));
}

// ============================================================================
// Prepass: xproj[t][row][g] = Wih0[g]·x[row][t] + bih0[g] + bhh0[g]
// ============================================================================
__global__ void __launch_bounds__(256)
xproj_kernel(const float* __restrict__ x,
             const float* __restrict__ Wih0,
             const float* __restrict__ bih0,
             const float* __restrict__ bhh0)
{
    __shared__ float sx[64 * IN];
    const int g   = threadIdx.x;
    const int row = blockIdx.y;
    const int t0  = blockIdx.x * 64;

    const float* xs = x + ((size_t)row * SEQ + t0) * IN;
    for (int i = g; i < 64 * IN / 4; i += 256)
        ((float4*)sx)[i] = ((const float4*)xs)[i];

    u64 w[IN / 2];
    const u64* wp = (const u64*)(Wih0 + g * IN);
#pragma unroll
    for (int k = 0; k < IN / 2; k++) w[k] = wp[k];
    const u64 bp = pk(bih0[g] + bhh0[g], 0.0f);
    __syncthreads();

    for (int tt = 0; tt < 64; tt++) {
        const ulonglong2* xv = (const ulonglong2*)(sx + tt * IN);
        u64 a = bp;
#pragma unroll
        for (int k = 0; k < IN / 4; k++) {
            ulonglong2 v = xv[k];
            a = fma2(w[2 * k],     v.x, a);
            a = fma2(w[2 * k + 1], v.y, a);
        }
        g_xproj[((size_t)(t0 + tt) * Bt + row) * GATES + g] = hsum(a);
    }
}

// ============================================================================
// Main: 128 CTAs x 1024 threads (32 warps). tid = g*4 + q (quarter K-split).
// Regs: quarter-rows of Whh0 + Wih1 (32 regs). Whh1 streamed from smem.
// Layer-pipelined: iteration u computes L0 gates(t=u) + L1 gates(t=u-1),
// both consuming the SAME h0(u-1) operand. 2 barriers/step. cp.async xproj.
// ============================================================================
__global__ void __launch_bounds__(1024, 1)
lstm2_q(const float* __restrict__ h0g,
        const float* __restrict__ c0g,
        const float* __restrict__ Whh0,
        const float* __restrict__ Wih1,
        const float* __restrict__ Whh1,
        const float* __restrict__ bih1,
        const float* __restrict__ bhh1,
        const float* __restrict__ Wh,
        const float* __restrict__ bhp,
        float* __restrict__ out)
{
    extern __shared__ float sm[];
    float* sW1 = sm;               // 16384  Whh1 row-major [256][64]
    float* sP  = sm + 16384;       // 4096   [layer][row][g][q]
    float* sXP = sP + 4096;        // 1024   [buf][row][g]
    float* sH0 = sXP + 1024;       // 256    [buf][row][j]
    float* sH1 = sH0 + 256;        // 256
    float* sWh = sH1 + 256;        // 64
    float* sPr = sWh + 64;         // 8      [parity][4]

    const int tid = threadIdx.x;
    const int g   = tid >> 2;            // 0..255
    const int q   = tid & 3;             // 0..3
    const int r0  = blockIdx.x * 2;

    // quarter-row register weights (16 floats = 8 u64 each)
    u64 wh0q[8], wx1q[8];
    {
        const u64* p0 = (const u64*)(Whh0 + g * Hs + q * 16);
        const u64* p1 = (const u64*)(Wih1 + g * Hs + q * 16);
#pragma unroll
        for (int k = 0; k < 8; k++) { wh0q[k] = p0[k]; wx1q[k] = p1[k]; }
    }
    const float b1  = bih1[g] + bhh1[g];
    const float bh0 = bhp[0];

    // smem init
    for (int i = tid; i < 4096; i += 1024)
        ((float4*)sW1)[i] = ((const float4*)Whh1)[i];
    if (tid < 64) sWh[tid] = Wh[tid];

    // state (updater threads tid<256: layer=tid>>7, row=(tid>>6)&1, j=tid&63)
    float c = 0.0f, hl = 0.0f;
    if (tid < 256) {
        int layer = tid >> 7, row = (tid >> 6) & 1, j = tid & 63;
        c  = c0g[(size_t)layer * Bt * Hs + (size_t)(r0 + row) * Hs + j];
        hl = h0g[(size_t)layer * Bt * Hs + (size_t)(r0 + row) * Hs + j];
        if (layer == 0) {
            sH0[row * 64 + j] = hl; sH0[128 + row * 64 + j] = hl;
        } else {
            sH1[row * 64 + j] = hl; sH1[128 + row * 64 + j] = hl;
        }
    }
    // xproj(t=0) into buf 0
    if (tid < 128) {
        cpasync16(sXP + tid * 4,
                  g_xproj + ((size_t)0 * Bt + r0) * GATES + tid * 4);
        asm volatile("cp.async.commit_group;");
        asm volatile("cp.async.wait_group 0;");
    }
    __syncthreads();

    for (int u = 0; u <= SEQ; u++) {
        // async prefetch xproj(u+1) into alternate buffer
        if (tid < 128 && u + 1 < SEQ) {
            cpasync16(sXP + ((u + 1) & 1) * 512 + tid * 4,
                      g_xproj + ((size_t)(u + 1) * Bt + r0) * GATES + tid * 4);
            asm volatile("cp.async.commit_group;");
        }

        const ulonglong2* H0 = (const ulonglong2*)(sH0 + (u & 1) * 128);
        const ulonglong2* H1 = (const ulonglong2*)(sH1 + (u & 1) * 128);
        const ulonglong2* W1 = (const ulonglong2*)sW1 + g * 16 + q * 4;

        float xp0 = sXP[(u & 1) * 512 + g];
        float xp1 = sXP[(u & 1) * 512 + 256 + g];
        u64 a0, a1, z0, z1;
        if (q == 0) { a0 = pk(xp0, 0.f); a1 = pk(xp1, 0.f); z0 = pk(b1, 0.f); z1 = z0; }
        else        { a0 = 0ULL; a1 = 0ULL; z0 = 0ULL; z1 = 0ULL; }

#pragma unroll
        for (int i = 0; i < 4; i++) {      // h0(u-1) feeds Whh0 AND Wih1
            ulonglong2 v0 = H0[q * 4 + i];
            ulonglong2 v1 = H0[16 + q * 4 + i];
            a0 = fma2(wh0q[2*i],   v0.x, a0);
            a0 = fma2(wh0q[2*i+1], v0.y, a0);
            a1 = fma2(wh0q[2*i],   v1.x, a1);
            a1 = fma2(wh0q[2*i+1], v1.y, a1);
            z0 = fma2(wx1q[2*i],   v0.x, z0);
            z0 = fma2(wx1q[2*i+1], v0.y, z0);
            z1 = fma2(wx1q[2*i],   v1.x, z1);
            z1 = fma2(wx1q[2*i+1], v1.y, z1);
        }
#pragma unroll
        for (int i = 0; i < 4; i++) {      // Whh1 (smem) over h1(u-2)
            ulonglong2 w  = W1[i];
            ulonglong2 u0 = H1[q * 4 + i];
            ulonglong2 u1 = H1[16 + q * 4 + i];
            z0 = fma2(w.x, u0.x, z0);
            z0 = fma2(w.y, u0.y, z0);
            z1 = fma2(w.x, u1.x, z1);
            z1 = fma2(w.y, u1.y, z1);
        }

        if (u < SEQ) {
            sP[(g << 2) + q]        = hsum(a0);
            sP[1024 + (g << 2) + q] = hsum(a1);
        }
        if (u >= 1) {
            sP[2048 + (g << 2) + q] = hsum(z0);
            sP[3072 + (g << 2) + q] = hsum(z1);
        }

        // head output for t=u-2 (partials from iteration u-1)
        if (u >= 2 && (tid == 256 || tid == 257)) {
            int row = tid - 256;
            float v = sPr[((u - 1) & 1) * 4 + row * 2]
                    + sPr[((u - 1) & 1) * 4 + row * 2 + 1] + bh0;
            out[(size_t)(r0 + row) * SEQ + (u - 2)] = sigf(v);
        }

        if (tid < 128)
            asm volatile("cp.async.wait_group 0;");
        __syncthreads();

        // ---------- phase 2: combine + activate + update ----------
        if (tid < 256) {
            int layer = tid >> 7, row = (tid >> 6) & 1, j = tid & 63;
            const float4* P4 = (const float4*)(sP + ((layer * 2 + row) << 10));
            float4 vi = P4[j], vf = P4[64 + j], vg = P4[128 + j], vo = P4[192 + j];
            float I = (vi.x + vi.y) + (vi.z + vi.w);
            float F = (vf.x + vf.y) + (vf.z + vf.w);
            float G = (vg.x + vg.y) + (vg.z + vg.w);
            float O = (vo.x + vo.y) + (vo.z + vo.w);
            float si = sigf(I), sf = sigf(F), sg = tanhfa(G), so = sigf(O);
            float cn = sf * c + si * sg;
            float hn = so * tanhfa(cn);
            bool act = layer ? (u >= 1) : (u < SEQ);
            if (act) {
                c = cn; hl = hn;
                if (layer == 0) sH0[((u + 1) & 1) * 128 + row * 64 + j] = hn;
                else            sH1[((u + 1) & 1) * 128 + row * 64 + j] = hn;
            }
            if (layer == 1) {   // head partials (warps 4..7)
                float p = act ? hn * sWh[j] : 0.0f;
#pragma unroll
                for (int off = 16; off; off >>= 1)
                    p += __shfl_down_sync(0xffffffffu, p, off);
                if ((tid & 31) == 0) sPr[(u & 1) * 4 + ((tid >> 5) - 4)] = p;
            }
        }
        __syncthreads();
    }

    // final head output for t=SEQ-1 (partials written at u=SEQ)
    if (tid == 256 || tid == 257) {
        int row = tid - 256;
        float v = sPr[(SEQ & 1) * 4 + row * 2]
                + sPr[(SEQ & 1) * 4 + row * 2 + 1] + bh0;
        out[(size_t)(r0 + row) * SEQ + (SEQ - 1)] = sigf(v);
    }

    // final h, c (held in updater registers)
    if (tid < 256) {
        int layer = tid >> 7, row = (tid >> 6) & 1, j = tid & 63;
        const size_t hb = (size_t)Bt * SEQ;
        const size_t cb = hb + 2 * (size_t)Bt * Hs;
        out[hb + (size_t)layer * Bt * Hs + (size_t)(r0 + row) * Hs + j] = hl;
        out[cb + (size_t)layer * Bt * Hs + (size_t)(r0 + row) * Hs + j] = c;
    }
}

extern "C" void kernel_launch(void* const* d_in, const int* in_sizes, int n_in,
                              void* d_out, int out_size)
{
    const float* x    = (const float*)d_in[0];
    const float* h0   = (const float*)d_in[1];
    const float* c0   = (const float*)d_in[2];
    const float* Wih0 = (const float*)d_in[3];
    const float* Whh0 = (const float*)d_in[4];
    const float* bih0 = (const float*)d_in[5];
    const float* bhh0 = (const float*)d_in[6];
    const float* Wih1 = (const float*)d_in[7];
    const float* Whh1 = (const float*)d_in[8];
    const float* bih1 = (const float*)d_in[9];
    const float* bhh1 = (const float*)d_in[10];
    const float* Wh   = (const float*)d_in[11];
    const float* bh   = (const float*)d_in[12];
    float* out = (float*)d_out;

    dim3 pre_grid(SEQ / 64, Bt);
    xproj_kernel<<<pre_grid, 256>>>(x, Wih0, bih0, bhh0);

    const int smem_bytes = (16384 + 4096 + 1024 + 256 + 256 + 64 + 8) * 4;
    cudaFuncSetAttribute(lstm2_q,
                         cudaFuncAttributeMaxDynamicSharedMemorySize, smem_bytes);
    lstm2_q<<<Bt / 2, 1024, smem_bytes>>>(h0, c0, Whh0, Wih1, Whh1,
                                          bih1, bhh1, Wh, bh, out);
}

// round 7
// speedup vs baseline: 4.3830x; 4.3830x over previous
#include <cuda_runtime.h>
#include <math.h>

#define Hs    64
#define SEQ   2048
#define Bt    256
#define IN    32
#define GATES 256   // 4*H

typedef unsigned long long u64;

__device__ float g_xproj[(size_t)SEQ * Bt * GATES];   // [t][row][g], bias0 folded

__device__ __forceinline__ u64 fma2(u64 a, u64 b, u64 c) {
    u64 d;
    asm("fma.rn.f32x2 %0, %1, %2, %3;" : "=l"(d) : "l"(a), "l"(b), "l"(c));
    return d;
}
__device__ __forceinline__ u64 pk(float a, float b) {
    u64 r;
    asm("mov.b64 %0, {%1, %2};" : "=l"(r) : "f"(a), "f"(b));
    return r;
}
__device__ __forceinline__ float hsum(u64 v) {
    float a, b;
    asm("mov.b64 {%0, %1}, %2;" : "=f"(a), "=f"(b) : "l"(v));
    return a + b;
}
__device__ __forceinline__ float ex2a(float x) {
    float y; asm("ex2.approx.f32 %0, %1;" : "=f"(y) : "f"(x)); return y;
}
__device__ __forceinline__ float rcpa(float x) {
    float y; asm("rcp.approx.f32 %0, %1;" : "=f"(y) : "f"(x)); return y;
}
__device__ __forceinline__ float sigf(float x) {
    return rcpa(1.0f + ex2a(-1.4426950408889634f * x));
}
__device__ __forceinline__ float tanhfa(float x) {
    return fmaf(2.0f, sigf(2.0f * x), -1.0f);
}

// ============================================================================
// Prepass: xproj[t][row][g] = Wih0[g]·x[row][t] + bih0[g] + bhh0[g]
// 256 threads = 64 gate-quads (tx) x 4 time-lanes (ty). Weights for 4 gates
// held in registers and reused over 16 timesteps; STG.128 output.
// ============================================================================
__global__ void __launch_bounds__(256)
xproj_kernel(const float* __restrict__ x,
             const float* __restrict__ Wih0,
             const float* __restrict__ bih0,
             const float* __restrict__ bhh0)
{
    __shared__ float sx[64 * IN];
    const int tid = threadIdx.x;
    const int tx  = tid & 63;        // gate quad: gates [tx*4, tx*4+4)
    const int ty  = tid >> 6;        // time lane 0..3
    const int row = blockIdx.y;
    const int t0  = blockIdx.x * 64;

    const float* xs = x + ((size_t)row * SEQ + t0) * IN;
    for (int i = tid; i < 64 * IN / 4; i += 256)
        ((float4*)sx)[i] = ((const float4*)xs)[i];

    u64 w[4][IN / 2];
    float b[4];
#pragma unroll
    for (int jj = 0; jj < 4; jj++) {
        const u64* wp = (const u64*)(Wih0 + (tx * 4 + jj) * IN);
#pragma unroll
        for (int k = 0; k < IN / 2; k++) w[jj][k] = wp[k];
        b[jj] = bih0[tx * 4 + jj] + bhh0[tx * 4 + jj];
    }
    __syncthreads();

    for (int tt = ty; tt < 64; tt += 4) {
        const ulonglong2* xv = (const ulonglong2*)(sx + tt * IN);
        u64 a0 = pk(b[0], 0.f), a1 = pk(b[1], 0.f);
        u64 a2 = pk(b[2], 0.f), a3 = pk(b[3], 0.f);
#pragma unroll
        for (int k = 0; k < IN / 4; k++) {
            ulonglong2 v = xv[k];
            a0 = fma2(w[0][2*k], v.x, a0); a0 = fma2(w[0][2*k+1], v.y, a0);
            a1 = fma2(w[1][2*k], v.x, a1); a1 = fma2(w[1][2*k+1], v.y, a1);
            a2 = fma2(w[2][2*k], v.x, a2); a2 = fma2(w[2][2*k+1], v.y, a2);
            a3 = fma2(w[3][2*k], v.x, a3); a3 = fma2(w[3][2*k+1], v.y, a3);
        }
        float4 r = make_float4(hsum(a0), hsum(a1), hsum(a2), hsum(a3));
        *(float4*)(g_xproj + ((size_t)(t0 + tt) * Bt + row) * GATES + tx * 4) = r;
    }
}

// ============================================================================
// Main: 128 CTAs x 512 threads (16 warps). tid = g + half*256 (half K-split).
// Thread holds half-rows of Whh0, Wih1, Whh1 in regs (96 regs). Layer-
// pipelined: iter u = L0 gates(t=u) + L1 gates(t=u-1), sharing the h0(u-1)
// operand. Head shfl-reduce deferred out of the critical section. 2 barriers.
// ============================================================================
__global__ void __launch_bounds__(512, 1)
lstm2_r7(const float* __restrict__ h0g,
         const float* __restrict__ c0g,
         const float* __restrict__ Whh0,
         const float* __restrict__ Wih1,
         const float* __restrict__ Whh1,
         const float* __restrict__ bih1,
         const float* __restrict__ bhh1,
         const float* __restrict__ Wh,
         const float* __restrict__ bhp,
         float* __restrict__ out)
{
    __shared__ float sP[4 * 512];    // [layer*2+row][g*2+half]
    __shared__ float sH0[2 * Hs];    // [row][j]
    __shared__ float sH1[2 * Hs];
    __shared__ float sPr[8];         // [parity][4]

    const int tid  = threadIdx.x;
    const int g    = tid & 255;
    const int half = tid >> 8;
    const int r0   = blockIdx.x * 2;

    // register weights: half-rows (32 floats = 16 u64 each)
    u64 wh0[16], wx1[16], wh1[16];
    {
        const u64* p0 = (const u64*)(Whh0 + g * Hs + half * 32);
        const u64* p1 = (const u64*)(Wih1 + g * Hs + half * 32);
        const u64* p2 = (const u64*)(Whh1 + g * Hs + half * 32);
#pragma unroll
        for (int k = 0; k < 16; k++) { wh0[k] = p0[k]; wx1[k] = p1[k]; wh1[k] = p2[k]; }
    }
    const float b1  = bih1[g] + bhh1[g];
    const float bh0 = bhp[0];
    const float whj = Wh[tid & 63];      // used by L1 updaters only

    float c = 0.0f, hn_prev = 0.0f;
    if (tid < 128) {                     // L0 updaters (warps 0-3)
        int r = tid >> 6, j = tid & 63;
        sH0[r * 64 + j] = h0g[(size_t)(r0 + r) * Hs + j];
        c = c0g[(size_t)(r0 + r) * Hs + j];
    }
    if (tid >= 256 && tid < 384) {       // L1 updaters (warps 8-11)
        int ub = tid - 256, r = ub >> 6, j = ub & 63;
        sH1[r * 64 + j] = h0g[(size_t)Bt * Hs + (size_t)(r0 + r) * Hs + j];
        c = c0g[(size_t)Bt * Hs + (size_t)(r0 + r) * Hs + j];
    }
    // xproj(t=0) prefetched into regs (half-0 threads only)
    float xp0 = 0.f, xp1 = 0.f;
    if (half == 0) {
        xp0 = g_xproj[((size_t)0 * Bt + r0) * GATES + g];
        xp1 = g_xproj[((size_t)0 * Bt + r0 + 1) * GATES + g];
    }
    __syncthreads();

    for (int u = 0; u <= SEQ; u++) {
        // prefetch xproj(u+1)
        float xpn0 = 0.f, xpn1 = 0.f;
        if (half == 0 && u + 1 < SEQ) {
            xpn0 = g_xproj[((size_t)(u + 1) * Bt + r0) * GATES + g];
            xpn1 = g_xproj[((size_t)(u + 1) * Bt + r0 + 1) * GATES + g];
        }

        // deferred head reduce for t=u-2 (hn_prev from iter u-1's L1 update)
        if (tid >= 256 && tid < 384 && u >= 2) {
            float p = hn_prev * whj;
#pragma unroll
            for (int off = 16; off; off >>= 1)
                p += __shfl_down_sync(0xffffffffu, p, off);
            if ((tid & 31) == 0) sPr[(u & 1) * 4 + ((tid >> 5) - 8)] = p;
        }

        // ---------- phase 1: partial gates ----------
        {
            const ulonglong2* H0 = (const ulonglong2*)sH0;
            const ulonglong2* H1 = (const ulonglong2*)sH1;
            u64 a0, a1, q0, q1;
            if (half == 0) { a0 = pk(xp0, 0.f); a1 = pk(xp1, 0.f);
                             q0 = pk(b1, 0.f);  q1 = q0; }
            else           { a0 = 0ULL; a1 = 0ULL; q0 = 0ULL; q1 = 0ULL; }
#pragma unroll
            for (int k = 0; k < 8; k++) {      // h0(u-1) feeds Whh0 AND Wih1
                ulonglong2 v0 = H0[half * 8 + k];
                ulonglong2 v1 = H0[16 + half * 8 + k];
                a0 = fma2(wh0[2*k],   v0.x, a0);
                a0 = fma2(wh0[2*k+1], v0.y, a0);
                a1 = fma2(wh0[2*k],   v1.x, a1);
                a1 = fma2(wh0[2*k+1], v1.y, a1);
                q0 = fma2(wx1[2*k],   v0.x, q0);
                q0 = fma2(wx1[2*k+1], v0.y, q0);
                q1 = fma2(wx1[2*k],   v1.x, q1);
                q1 = fma2(wx1[2*k+1], v1.y, q1);
            }
            if (u < SEQ) {
                sP[g * 2 + half]       = hsum(a0);
                sP[512 + g * 2 + half] = hsum(a1);
            }
#pragma unroll
            for (int k = 0; k < 8; k++) {      // Whh1 over h1(u-2)
                ulonglong2 v0 = H1[half * 8 + k];
                ulonglong2 v1 = H1[16 + half * 8 + k];
                q0 = fma2(wh1[2*k],   v0.x, q0);
                q0 = fma2(wh1[2*k+1], v0.y, q0);
                q1 = fma2(wh1[2*k],   v1.x, q1);
                q1 = fma2(wh1[2*k+1], v1.y, q1);
            }
            if (u >= 1) {
                sP[1024 + g * 2 + half] = hsum(q0);
                sP[1536 + g * 2 + half] = hsum(q1);
            }
        }
        xp0 = xpn0; xp1 = xpn1;
        __syncthreads();

        // ---------- phase 2: combine + activate + update ----------
        if (tid < 128 && u < SEQ) {            // L0: time u
            int r = tid >> 6, j = tid & 63;
            const float2* p = (const float2*)(sP + r * 512);
            float2 vi = p[j], vf = p[64 + j], vg = p[128 + j], vo = p[192 + j];
            float si = sigf(vi.x + vi.y);
            float sf = sigf(vf.x + vf.y);
            float sg = tanhfa(vg.x + vg.y);
            float so = sigf(vo.x + vo.y);
            c = sf * c + si * sg;
            sH0[r * 64 + j] = so * tanhfa(c);
        }
        if (tid >= 256 && tid < 384 && u >= 1) {   // L1: time u-1
            int ub = tid - 256, r = ub >> 6, j = ub & 63;
            const float2* p = (const float2*)(sP + (2 + r) * 512);
            float2 vi = p[j], vf = p[64 + j], vg = p[128 + j], vo = p[192 + j];
            float si = sigf(vi.x + vi.y);
            float sf = sigf(vf.x + vf.y);
            float sg = tanhfa(vg.x + vg.y);
            float so = sigf(vo.x + vo.y);
            c = sf * c + si * sg;
            float hn = so * tanhfa(c);
            sH1[r * 64 + j] = hn;
            hn_prev = hn;                      // reduced at top of next iter
        }
        if (u >= 2 && (tid == 384 || tid == 385)) {  // head out, t=u-2
            int row = tid - 384;
            float v = sPr[(u & 1) * 4 + row * 2]
                    + sPr[(u & 1) * 4 + row * 2 + 1] + bh0;
            out[(size_t)(r0 + row) * SEQ + (u - 2)] = sigf(v);
        }
        __syncthreads();
    }

    // post-loop: reduce hn_prev (L1 t=SEQ-1) and emit last head sample
    if (tid >= 256 && tid < 384) {
        float p = hn_prev * whj;
#pragma unroll
        for (int off = 16; off; off >>= 1)
            p += __shfl_down_sync(0xffffffffu, p, off);
        if ((tid & 31) == 0) sPr[4 + ((tid >> 5) - 8)] = p;
    }
    __syncthreads();
    if (tid == 384 || tid == 385) {
        int row = tid - 384;
        float v = sPr[4 + row * 2] + sPr[4 + row * 2 + 1] + bh0;
        out[(size_t)(r0 + row) * SEQ + (SEQ - 1)] = sigf(v);
    }

    // final h, c
    const size_t hb = (size_t)Bt * SEQ;
    const size_t cb = hb + 2 * (size_t)Bt * Hs;
    if (tid < 128) {
        int r = tid >> 6, j = tid & 63;
        out[hb + (size_t)(r0 + r) * Hs + j] = sH0[r * 64 + j];
        out[cb + (size_t)(r0 + r) * Hs + j] = c;
    }
    if (tid >= 256 && tid < 384) {
        int ub = tid - 256, r = ub >> 6, j = ub & 63;
        out[hb + Bt * Hs + (size_t)(r0 + r) * Hs + j] = sH1[r * 64 + j];
        out[cb + Bt * Hs + (size_t)(r0 + r) * Hs + j] = c;
    }
}

extern "C" void kernel_launch(void* const* d_in, const int* in_sizes, int n_in,
                              void* d_out, int out_size)
{
    const float* x    = (const float*)d_in[0];
    const float* h0   = (const float*)d_in[1];
    const float* c0   = (const float*)d_in[2];
    const float* Wih0 = (const float*)d_in[3];
    const float* Whh0 = (const float*)d_in[4];
    const float* bih0 = (const float*)d_in[5];
    const float* bhh0 = (const float*)d_in[6];
    const float* Wih1 = (const float*)d_in[7];
    const float* Whh1 = (const float*)d_in[8];
    const float* bih1 = (const float*)d_in[9];
    const float* bhh1 = (const float*)d_in[10];
    const float* Wh   = (const float*)d_in[11];
    const float* bh   = (const float*)d_in[12];
    float* out = (float*)d_out;

    dim3 pre_grid(SEQ / 64, Bt);
    xproj_kernel<<<pre_grid, 256>>>(x, Wih0, bih0, bhh0);
    lstm2_r7<<<Bt / 2, 512>>>(h0, c0, Whh0, Wih1, Whh1,
                              bih1, bhh1, Wh, bh, out);
}